// round 16
// baseline (speedup 1.0000x reference)
#include <cuda_runtime.h>
#include <cstdint>

#define N_NODES 50000
#define N_EDGES 800000
#define DIN     128
#define DH      128         // H * D_OUT
#define NH      2
#define DC      64          // per-head channels
#define NEG_SLOPE 0.2f
#define LN_EPS  1e-5f
#define BSTRIDE 96          // bucket capacity per node (Poisson(16) tail ~0 at 96)

typedef unsigned long long ull;

// ---------------- scratch (no allocations allowed) ----------------
__device__ __align__(16) float g_xl[N_NODES * DH];
__device__ __align__(16) float g_xr[N_NODES * DH];
__device__ __align__(16) float g_agg[N_NODES * DH];   // normalized weighted sum
__device__ __align__(16) int g_cnt[N_NODES];          // real in-degree per node
__device__ int g_esrc[N_NODES * BSTRIDE];             // bucketed src lists

__device__ __forceinline__ float lrelu(float x) {
    return x > 0.f ? x : NEG_SLOPE * x;
}

// ---- packed f32x2 helpers (B300: FFMA2 doubles fp32 FMA issue rate) ----
__device__ __forceinline__ ull pack2(float lo, float hi) {
    ull r;
    asm("mov.b64 %0, {%1, %2};" : "=l"(r) : "f"(lo), "f"(hi));
    return r;
}
__device__ __forceinline__ void ffma2(ull& d, ull a, ull b) {
    asm("fma.rn.f32x2 %0, %1, %2, %3;" : "=l"(d) : "l"(a), "l"(b), "l"(d));
}
__device__ __forceinline__ float2 unpack2(ull v) {
    float lo, hi;
    asm("mov.b64 {%0, %1}, %2;" : "=f"(lo), "=f"(hi) : "l"(v));
    return make_float2(lo, hi);
}

// -------- kernel 0a: zero degree counters (must complete before bucketing) ----
__global__ void k_zero() {
    int i = blockIdx.x * blockDim.x + threadIdx.x;
    if (i < N_NODES) g_cnt[i] = 0;
}

// -------- kernel 0b: passthrough outputs + direct bucket scatter (fused) ------
__global__ void k_init(const int* __restrict__ E,
                       const float* __restrict__ attr,
                       float* __restrict__ outE,
                       float* __restrict__ outA) {
    int stride = gridDim.x * blockDim.x;
    int i0 = blockIdx.x * blockDim.x + threadIdx.x;
    for (int i = i0; i < N_EDGES; i += stride) {
        int s = E[i];
        int d = E[N_EDGES + i];
        outE[i] = (float)s;
        outE[N_EDGES + i] = (float)d;
        outA[i] = attr[i];
        int pos = atomicAdd(&g_cnt[d], 1);
        if (pos < BSTRIDE) g_esrc[d * BSTRIDE + pos] = s;
    }
}

// ---------------- kernel 1: x_l / x_r node transforms (FFMA2) ----------------
#define TM 16
__global__ __launch_bounds__(128) void k_gemm(const float* __restrict__ X,
                                              const float* __restrict__ Wl,
                                              const float* __restrict__ bl,
                                              const float* __restrict__ Wr,
                                              const float* __restrict__ br) {
    __shared__ __align__(16) float sx[TM * 128];
    int j  = threadIdx.x;
    int n0 = blockIdx.x * TM;
#pragma unroll
    for (int m = 0; m < TM; m++)
        sx[m * 128 + j] = X[(n0 + m) * 128 + j];
    __syncthreads();

    ull accl2[TM], accr2[TM];
#pragma unroll
    for (int m = 0; m < TM; m++) { accl2[m] = 0ull; accr2[m] = 0ull; }

#pragma unroll 2
    for (int k = 0; k < 128; k += 2) {
        ull wl2 = pack2(Wl[k * 128 + j], Wl[(k + 1) * 128 + j]);
        ull wr2 = pack2(Wr[k * 128 + j], Wr[(k + 1) * 128 + j]);
#pragma unroll
        for (int m = 0; m < TM; m++) {
            ull x2 = *(const ull*)(sx + m * 128 + k);
            ffma2(accl2[m], x2, wl2);
            ffma2(accr2[m], x2, wr2);
        }
    }
    float bjl = bl[j], bjr = br[j];
#pragma unroll
    for (int m = 0; m < TM; m++) {
        float2 fl = unpack2(accl2[m]);
        float2 fr = unpack2(accr2[m]);
        g_xl[(n0 + m) * 128 + j] = fl.x + fl.y + bjl;
        g_xr[(n0 + m) * 128 + j] = fr.x + fr.y + bjr;
    }
}

// ---------------- kernel 2: gather edge pass (warp per node, no atomics) ------
// 4-edge software pipeline; self-loop (src=n) handled as the first term.
__device__ __forceinline__ float edge_score(const float4& a, const float4& b,
                                            const float4& t) {
    return t.x * lrelu(a.x + b.x) + t.y * lrelu(a.y + b.y)
         + t.z * lrelu(a.z + b.z) + t.w * lrelu(a.w + b.w);
}

__global__ __launch_bounds__(256) void k_edge(const float* __restrict__ att) {
    int n = blockIdx.x * 8 + (threadIdx.x >> 5);
    if (n >= N_NODES) return;
    int lane = threadIdx.x & 31;
    int head = lane >> 4;
    int q    = lane & 15;
    int base = head * DC + q * 4;

    float4 b = *(const float4*)(g_xr + (size_t)n * 128 + base);
    float4 t = __ldg((const float4*)(att + base));

    // self loop first: src = n, a = xl[n]
    float4 aself = *(const float4*)(g_xl + (size_t)n * 128 + base);
    float scs = edge_score(aself, b, t);
#pragma unroll
    for (int off = 1; off < 16; off <<= 1)
        scs += __shfl_xor_sync(0xffffffffu, scs, off, 16);
    float ws = __expf(fminf(scs, 60.f));
    float den = ws;
    float4 acc = make_float4(ws * aself.x, ws * aself.y, ws * aself.z, ws * aself.w);

    int deg = g_cnt[n];
    const int* bucket = g_esrc + (size_t)n * BSTRIDE;

    int p = 0;
    for (; p + 4 <= deg; p += 4) {
        int s0 = __ldg(bucket + p);
        int s1 = __ldg(bucket + p + 1);
        int s2 = __ldg(bucket + p + 2);
        int s3 = __ldg(bucket + p + 3);
        float4 a0 = *(const float4*)(g_xl + (size_t)s0 * 128 + base);
        float4 a1 = *(const float4*)(g_xl + (size_t)s1 * 128 + base);
        float4 a2 = *(const float4*)(g_xl + (size_t)s2 * 128 + base);
        float4 a3 = *(const float4*)(g_xl + (size_t)s3 * 128 + base);
        float c0 = edge_score(a0, b, t);
        float c1 = edge_score(a1, b, t);
        float c2 = edge_score(a2, b, t);
        float c3 = edge_score(a3, b, t);
#pragma unroll
        for (int off = 1; off < 16; off <<= 1) {
            c0 += __shfl_xor_sync(0xffffffffu, c0, off, 16);
            c1 += __shfl_xor_sync(0xffffffffu, c1, off, 16);
            c2 += __shfl_xor_sync(0xffffffffu, c2, off, 16);
            c3 += __shfl_xor_sync(0xffffffffu, c3, off, 16);
        }
        float w0 = __expf(fminf(c0, 60.f));
        float w1 = __expf(fminf(c1, 60.f));
        float w2 = __expf(fminf(c2, 60.f));
        float w3 = __expf(fminf(c3, 60.f));
        den += (w0 + w1) + (w2 + w3);
        acc.x += w0 * a0.x + w1 * a1.x + w2 * a2.x + w3 * a3.x;
        acc.y += w0 * a0.y + w1 * a1.y + w2 * a2.y + w3 * a3.y;
        acc.z += w0 * a0.z + w1 * a1.z + w2 * a2.z + w3 * a3.z;
        acc.w += w0 * a0.w + w1 * a1.w + w2 * a2.w + w3 * a3.w;
    }
    for (; p < deg; p++) {
        int src = __ldg(bucket + p);
        float4 a = *(const float4*)(g_xl + (size_t)src * 128 + base);
        float sc = edge_score(a, b, t);
#pragma unroll
        for (int off = 1; off < 16; off <<= 1)
            sc += __shfl_xor_sync(0xffffffffu, sc, off, 16);
        float wt = __expf(fminf(sc, 60.f));
        den += wt;
        acc.x += wt * a.x; acc.y += wt * a.y;
        acc.z += wt * a.z; acc.w += wt * a.w;
    }
    float inv = 1.f / den;
    *(float4*)(g_agg + (size_t)n * 128 + base) =
        make_float4(acc.x * inv, acc.y * inv, acc.z * inv, acc.w * inv);
}

// ---------------- kernel 3: +bias, final linear, LayerNorm ----------------
#define NPB 16
__global__ __launch_bounds__(128) void k_final(const float* __restrict__ bias,
                                               const float* __restrict__ Wf,
                                               const float* __restrict__ bf,
                                               const float* __restrict__ gamma,
                                               const float* __restrict__ beta,
                                               float* __restrict__ out) {
    __shared__ __align__(16) float sht[128 * 20];   // [k][16 nodes + pad4]
    __shared__ float rs[4][8], rq[4][8];
    int tid = threadIdx.x;
    int n0  = blockIdx.x * NPB;
    int c   = tid & 63;
    int g   = tid >> 6;          // 0 or 1: which group of 8 nodes
    int nb  = g * 8;

#pragma unroll
    for (int i = tid; i < NPB * 128; i += 128) {
        int nn = i >> 7, cc = i & 127;
        sht[cc * 20 + nn] = g_agg[(size_t)(n0 + nn) * 128 + cc] + bias[cc];
    }
    __syncthreads();

    ull acc2[4];
    float b0 = bf[c];
#pragma unroll
    for (int jj = 0; jj < 4; jj++) acc2[jj] = pack2(b0, b0);

#pragma unroll 4
    for (int k = 0; k < 128; k++) {
        float wv = Wf[k * 64 + c];
        ull wv2 = pack2(wv, wv);
        const ull* row = (const ull*)(sht + k * 20 + nb);   // 8-aligned (nb even, pad 20)
        ffma2(acc2[0], row[0], wv2);
        ffma2(acc2[1], row[1], wv2);
        ffma2(acc2[2], row[2], wv2);
        ffma2(acc2[3], row[3], wv2);
    }
    float acc[8];
#pragma unroll
    for (int jj = 0; jj < 4; jj++) {
        float2 f = unpack2(acc2[jj]);
        acc[2 * jj] = f.x; acc[2 * jj + 1] = f.y;
    }

    float s[8], sq[8];
#pragma unroll
    for (int jj = 0; jj < 8; jj++) { s[jj] = acc[jj]; sq[jj] = acc[jj] * acc[jj]; }
#pragma unroll
    for (int off = 16; off; off >>= 1) {
#pragma unroll
        for (int jj = 0; jj < 8; jj++) {
            s[jj]  += __shfl_xor_sync(0xffffffffu, s[jj],  off);
            sq[jj] += __shfl_xor_sync(0xffffffffu, sq[jj], off);
        }
    }
    int wid = tid >> 5;
    if ((tid & 31) == 0) {
#pragma unroll
        for (int jj = 0; jj < 8; jj++) { rs[wid][jj] = s[jj]; rq[wid][jj] = sq[jj]; }
    }
    __syncthreads();
    int wb = g << 1;
    float gm = gamma[c], bt = beta[c];
#pragma unroll
    for (int jj = 0; jj < 8; jj++) {
        float S = rs[wb][jj] + rs[wb + 1][jj];
        float Q = rq[wb][jj] + rq[wb + 1][jj];
        float mean = S * (1.f / 64.f);
        float var  = Q * (1.f / 64.f) - mean * mean;
        float r    = rsqrtf(var + LN_EPS);
        out[(size_t)(n0 + nb + jj) * 64 + c] = (acc[jj] - mean) * r * gm + bt;
    }
}

// ---------------- launcher ----------------
extern "C" void kernel_launch(void* const* d_in, const int* in_sizes, int n_in,
                              void* d_out, int out_size) {
    const float* X     = (const float*)d_in[0];
    const int*   E     = (const int*)  d_in[1];
    const float* attr  = (const float*)d_in[2];
    const float* W_l   = (const float*)d_in[3];
    const float* b_l   = (const float*)d_in[4];
    const float* W_r   = (const float*)d_in[5];
    const float* b_r   = (const float*)d_in[6];
    const float* att   = (const float*)d_in[7];
    const float* bias  = (const float*)d_in[8];
    const float* W_f   = (const float*)d_in[9];
    const float* b_f   = (const float*)d_in[10];
    const float* gamma = (const float*)d_in[11];
    const float* beta  = (const float*)d_in[12];
    float* out = (float*)d_out;

    (void)in_sizes; (void)n_in; (void)out_size;

    float* outE = out + (size_t)N_NODES * 64;
    float* outA = outE + (size_t)2 * N_EDGES;

    k_zero<<<(N_NODES + 255) / 256, 256>>>();
    k_init<<<832, 256>>>(E, attr, outE, outA);
    k_gemm<<<N_NODES / TM, 128>>>(X, W_l, b_l, W_r, b_r);
    k_edge<<<(N_NODES + 7) / 8, 256>>>(att);
    k_final<<<N_NODES / NPB, 128>>>(bias, W_f, b_f, gamma, beta, out);
}

// round 17
// speedup vs baseline: 1.3167x; 1.3167x over previous
#include <cuda_runtime.h>
#include <cstdint>

#define N_NODES 50000
#define N_EDGES 800000
#define ET      850000      // edges + self loops
#define DIN     128
#define DH      128         // H * D_OUT
#define NH      2
#define DC      64          // per-head channels
#define NEG_SLOPE 0.2f
#define LN_EPS  1e-5f

typedef unsigned long long ull;

// ---------------- scratch (no allocations allowed) ----------------
__device__ __align__(16) float g_xl[N_NODES * DH];
__device__ __align__(16) float g_xr[N_NODES * DH];
__device__ __align__(16) float g_agg[N_NODES * DH];   // normalized weighted sum
__device__ __align__(16) int g_cnt[N_NODES];          // dst degrees (init 1 = self loop)
__device__ int g_rowptr[N_NODES + 1]; // CSR row pointers
__device__ int g_woff[N_NODES];       // scatter write cursors
__device__ int g_esrc[ET];            // src node per CSR slot

__device__ __forceinline__ float lrelu(float x) {
    return x > 0.f ? x : NEG_SLOPE * x;
}

// ---- packed f32x2 helpers (B300: FFMA2 doubles fp32 FMA issue rate) ----
__device__ __forceinline__ ull pack2(float lo, float hi) {
    ull r;
    asm("mov.b64 %0, {%1, %2};" : "=l"(r) : "f"(lo), "f"(hi));
    return r;
}
__device__ __forceinline__ void ffma2(ull& d, ull a, ull b) {
    asm("fma.rn.f32x2 %0, %1, %2, %3;" : "=l"(d) : "l"(a), "l"(b), "l"(d));
}
__device__ __forceinline__ float2 unpack2(ull v) {
    float lo, hi;
    asm("mov.b64 {%0, %1}, %2;" : "=f"(lo), "=f"(hi) : "l"(v));
    return make_float2(lo, hi);
}

// -------- kernel 0a: init degree counters (must complete before histogram) ----
__global__ void k_zero() {
    int i = blockIdx.x * blockDim.x + threadIdx.x;
    if (i < N_NODES) g_cnt[i] = 1;   // 1 = the self loop
}

// -------- kernel 0b: passthrough outputs + dst histogram (fused) --------
__global__ void k_init(const int* __restrict__ E,
                       const float* __restrict__ attr,
                       float* __restrict__ outE,
                       float* __restrict__ outA) {
    int stride = gridDim.x * blockDim.x;
    int i0 = blockIdx.x * blockDim.x + threadIdx.x;
    for (int i = i0; i < N_EDGES; i += stride) {
        int s = E[i];
        int d = E[N_EDGES + i];
        outE[i] = (float)s;
        outE[N_EDGES + i] = (float)d;
        outA[i] = attr[i];
        atomicAdd(&g_cnt[d], 1);
    }
}

// ---------------- kernel 1: x_l / x_r node transforms (FFMA2) ----------------
#define TM 16
__global__ __launch_bounds__(128) void k_gemm(const float* __restrict__ X,
                                              const float* __restrict__ Wl,
                                              const float* __restrict__ bl,
                                              const float* __restrict__ Wr,
                                              const float* __restrict__ br) {
    __shared__ __align__(16) float sx[TM * 128];
    int j  = threadIdx.x;
    int n0 = blockIdx.x * TM;
#pragma unroll
    for (int m = 0; m < TM; m++)
        sx[m * 128 + j] = X[(n0 + m) * 128 + j];
    __syncthreads();

    ull accl2[TM], accr2[TM];
#pragma unroll
    for (int m = 0; m < TM; m++) { accl2[m] = 0ull; accr2[m] = 0ull; }

#pragma unroll 2
    for (int k = 0; k < 128; k += 2) {
        ull wl2 = pack2(Wl[k * 128 + j], Wl[(k + 1) * 128 + j]);
        ull wr2 = pack2(Wr[k * 128 + j], Wr[(k + 1) * 128 + j]);
#pragma unroll
        for (int m = 0; m < TM; m++) {
            ull x2 = *(const ull*)(sx + m * 128 + k);
            ffma2(accl2[m], x2, wl2);
            ffma2(accr2[m], x2, wr2);
        }
    }
    float bjl = bl[j], bjr = br[j];
#pragma unroll
    for (int m = 0; m < TM; m++) {
        float2 fl = unpack2(accl2[m]);
        float2 fr = unpack2(accr2[m]);
        g_xl[(n0 + m) * 128 + j] = fl.x + fl.y + bjl;
        g_xr[(n0 + m) * 128 + j] = fr.x + fr.y + bjr;
    }
}

// ---------------- exclusive scan: warp-shuffle based, 1024 threads -----------
__global__ __launch_bounds__(1024) void k_scan() {
    __shared__ int swarp[32];
    __shared__ int s_carry;
    int tid  = threadIdx.x;
    int lane = tid & 31;
    int wid  = tid >> 5;
    if (tid == 0) s_carry = 0;
    __syncthreads();
    const int CH = 4096;   // 1024 threads x 4 items
    for (int base = 0; base < N_NODES; base += CH) {
        int i0 = base + tid * 4;
        int4 v = make_int4(0, 0, 0, 0);
        if (i0 < N_NODES) v = *(const int4*)(g_cnt + i0);   // N_NODES % 4 == 0
        int sum = v.x + v.y + v.z + v.w;
        // warp inclusive scan of per-thread sums
        int incl = sum;
#pragma unroll
        for (int off = 1; off < 32; off <<= 1) {
            int t = __shfl_up_sync(0xffffffffu, incl, off);
            if (lane >= off) incl += t;
        }
        if (lane == 31) swarp[wid] = incl;
        __syncthreads();
        if (wid == 0) {
            int w = swarp[lane];
            int wi = w;
#pragma unroll
            for (int off = 1; off < 32; off <<= 1) {
                int t = __shfl_up_sync(0xffffffffu, wi, off);
                if (lane >= off) wi += t;
            }
            swarp[lane] = wi - w;   // exclusive prefix of warp sums
        }
        __syncthreads();
        int running = s_carry + swarp[wid] + (incl - sum);
        if (i0 < N_NODES) {
            int4 rp, wo;
            rp.x = running;            wo.x = rp.x;
            rp.y = running + v.x;      wo.y = rp.y;
            rp.z = rp.y + v.y;         wo.z = rp.z;
            rp.w = rp.z + v.z;         wo.w = rp.w;
            *(int4*)(g_rowptr + i0) = rp;
            *(int4*)(g_woff   + i0) = wo;
        }
        __syncthreads();
        // chunk total = exclusive-prefix-of-last-warp + last warp's inclusive
        if (tid == 1023) s_carry += swarp[wid] + incl;
        __syncthreads();
    }
    if (tid == 0) g_rowptr[N_NODES] = s_carry;
}

__global__ void k_scatter(const int* __restrict__ E) {
    int stride = gridDim.x * blockDim.x;
    for (int e = blockIdx.x * blockDim.x + threadIdx.x; e < ET; e += stride) {
        int src, dst;
        if (e < N_EDGES) { src = __ldg(E + e); dst = __ldg(E + N_EDGES + e); }
        else             { src = e - N_EDGES; dst = src; }
        int pos = atomicAdd(&g_woff[dst], 1);
        g_esrc[pos] = src;
    }
}

// ---------------- kernel 2: gather edge pass (warp per node, no atomics) ------
// 2-edge software pipeline: independent score chains double ILP.
__global__ __launch_bounds__(256) void k_edge(const float* __restrict__ att) {
    int n = blockIdx.x * 8 + (threadIdx.x >> 5);
    if (n >= N_NODES) return;
    int lane = threadIdx.x & 31;
    int head = lane >> 4;
    int q    = lane & 15;
    int base = head * DC + q * 4;

    float4 b = *(const float4*)(g_xr + (size_t)n * 128 + base);
    float4 t = __ldg((const float4*)(att + base));

    int s0 = g_rowptr[n], s1 = g_rowptr[n + 1];
    float4 acc = make_float4(0.f, 0.f, 0.f, 0.f);
    float den = 0.f;

    int p = s0;
    for (; p + 2 <= s1; p += 2) {
        int src0 = __ldg(g_esrc + p);
        int src1 = __ldg(g_esrc + p + 1);
        float4 a0 = *(const float4*)(g_xl + (size_t)src0 * 128 + base);
        float4 a1 = *(const float4*)(g_xl + (size_t)src1 * 128 + base);
        float sc0 = t.x * lrelu(a0.x + b.x) + t.y * lrelu(a0.y + b.y)
                  + t.z * lrelu(a0.z + b.z) + t.w * lrelu(a0.w + b.w);
        float sc1 = t.x * lrelu(a1.x + b.x) + t.y * lrelu(a1.y + b.y)
                  + t.z * lrelu(a1.z + b.z) + t.w * lrelu(a1.w + b.w);
#pragma unroll
        for (int off = 1; off < 16; off <<= 1) {
            sc0 += __shfl_xor_sync(0xffffffffu, sc0, off, 16);
            sc1 += __shfl_xor_sync(0xffffffffu, sc1, off, 16);
        }
        float w0 = __expf(fminf(sc0, 60.f));
        float w1 = __expf(fminf(sc1, 60.f));
        den += w0 + w1;
        acc.x += w0 * a0.x + w1 * a1.x;
        acc.y += w0 * a0.y + w1 * a1.y;
        acc.z += w0 * a0.z + w1 * a1.z;
        acc.w += w0 * a0.w + w1 * a1.w;
    }
    if (p < s1) {
        int src = __ldg(g_esrc + p);
        float4 a = *(const float4*)(g_xl + (size_t)src * 128 + base);
        float sc = t.x * lrelu(a.x + b.x) + t.y * lrelu(a.y + b.y)
                 + t.z * lrelu(a.z + b.z) + t.w * lrelu(a.w + b.w);
#pragma unroll
        for (int off = 1; off < 16; off <<= 1)
            sc += __shfl_xor_sync(0xffffffffu, sc, off, 16);
        float wt = __expf(fminf(sc, 60.f));
        den += wt;
        acc.x += wt * a.x; acc.y += wt * a.y;
        acc.z += wt * a.z; acc.w += wt * a.w;
    }
    float inv = 1.f / den;
    *(float4*)(g_agg + (size_t)n * 128 + base) =
        make_float4(acc.x * inv, acc.y * inv, acc.z * inv, acc.w * inv);
}

// ---------------- kernel 3: +bias, final linear, LayerNorm ----------------
#define NPB 16
__global__ __launch_bounds__(128) void k_final(const float* __restrict__ bias,
                                               const float* __restrict__ Wf,
                                               const float* __restrict__ bf,
                                               const float* __restrict__ gamma,
                                               const float* __restrict__ beta,
                                               float* __restrict__ out) {
    __shared__ __align__(16) float sht[128 * 20];   // row stride 20 -> 16B aligned
    __shared__ float rs[4][8], rq[4][8];
    int tid = threadIdx.x;
    int n0  = blockIdx.x * NPB;
    int c   = tid & 63;
    int g   = tid >> 6;          // 0 or 1: which group of 8 nodes
    int nb  = g * 8;

#pragma unroll
    for (int i = tid; i < NPB * 128; i += 128) {
        int nn = i >> 7, cc = i & 127;
        sht[cc * 20 + nn] = g_agg[(size_t)(n0 + nn) * 128 + cc] + bias[cc];
    }
    __syncthreads();

    ull acc2[4];
    float b0 = bf[c];
#pragma unroll
    for (int jj = 0; jj < 4; jj++) acc2[jj] = pack2(b0, b0);

#pragma unroll 4
    for (int k = 0; k < 128; k++) {
        float wv = Wf[k * 64 + c];
        ull wv2 = pack2(wv, wv);
        const ull* row = (const ull*)(sht + k * 20 + nb);   // 8B-aligned (nb even, stride 20)
        ffma2(acc2[0], row[0], wv2);
        ffma2(acc2[1], row[1], wv2);
        ffma2(acc2[2], row[2], wv2);
        ffma2(acc2[3], row[3], wv2);
    }
    float acc[8];
#pragma unroll
    for (int jj = 0; jj < 4; jj++) {
        float2 f = unpack2(acc2[jj]);
        acc[2 * jj] = f.x; acc[2 * jj + 1] = f.y;
    }

    float s[8], sq[8];
#pragma unroll
    for (int jj = 0; jj < 8; jj++) { s[jj] = acc[jj]; sq[jj] = acc[jj] * acc[jj]; }
#pragma unroll
    for (int off = 16; off; off >>= 1) {
#pragma unroll
        for (int jj = 0; jj < 8; jj++) {
            s[jj]  += __shfl_xor_sync(0xffffffffu, s[jj],  off);
            sq[jj] += __shfl_xor_sync(0xffffffffu, sq[jj], off);
        }
    }
    int wid = tid >> 5;
    if ((tid & 31) == 0) {
#pragma unroll
        for (int jj = 0; jj < 8; jj++) { rs[wid][jj] = s[jj]; rq[wid][jj] = sq[jj]; }
    }
    __syncthreads();
    int wb = g << 1;
    float gm = gamma[c], bt = beta[c];
#pragma unroll
    for (int jj = 0; jj < 8; jj++) {
        float S = rs[wb][jj] + rs[wb + 1][jj];
        float Q = rq[wb][jj] + rq[wb + 1][jj];
        float mean = S * (1.f / 64.f);
        float var  = Q * (1.f / 64.f) - mean * mean;
        float r    = rsqrtf(var + LN_EPS);
        out[(size_t)(n0 + nb + jj) * 64 + c] = (acc[jj] - mean) * r * gm + bt;
    }
}

// ---------------- launcher ----------------
extern "C" void kernel_launch(void* const* d_in, const int* in_sizes, int n_in,
                              void* d_out, int out_size) {
    const float* X     = (const float*)d_in[0];
    const int*   E     = (const int*)  d_in[1];
    const float* attr  = (const float*)d_in[2];
    const float* W_l   = (const float*)d_in[3];
    const float* b_l   = (const float*)d_in[4];
    const float* W_r   = (const float*)d_in[5];
    const float* b_r   = (const float*)d_in[6];
    const float* att   = (const float*)d_in[7];
    const float* bias  = (const float*)d_in[8];
    const float* W_f   = (const float*)d_in[9];
    const float* b_f   = (const float*)d_in[10];
    const float* gamma = (const float*)d_in[11];
    const float* beta  = (const float*)d_in[12];
    float* out = (float*)d_out;

    (void)in_sizes; (void)n_in; (void)out_size;

    float* outE = out + (size_t)N_NODES * 64;
    float* outA = outE + (size_t)2 * N_EDGES;

    k_zero<<<(N_NODES + 255) / 256, 256>>>();
    k_init<<<832, 256>>>(E, attr, outE, outA);
    k_scan<<<1, 1024>>>();
    k_scatter<<<832, 256>>>(E);
    k_gemm<<<N_NODES / TM, 128>>>(X, W_l, b_l, W_r, b_r);
    k_edge<<<(N_NODES + 7) / 8, 256>>>(att);
    k_final<<<N_NODES / NPB, 128>>>(bias, W_f, b_f, gamma, beta, out);
}